// round 2
// baseline (speedup 1.0000x reference)
#include <cuda_runtime.h>

// Problem constants (fixed shapes: pred[8192,7,7,30], gt[8192,7,7,30])
#define NCH        30
#define TPB        128           // threads per block = cells per block
#define MAX_BLOCKS 4096          // 401408/128 = 3136 actual

// Scratch (no device allocation allowed -> device globals)
__device__ float        g_partials[MAX_BLOCKS];
__device__ unsigned int g_count = 0;   // blocks-done counter (reset by last block)

__global__ __launch_bounds__(TPB)
void yolo_loss_fused(const float* __restrict__ pred,
                     const float* __restrict__ gt,
                     float* __restrict__ out,
                     int n_cells, int n_blocks, float inv_batch)
{
    __shared__ float s_pred[TPB * NCH];   // 15360 B
    __shared__ float s_gt  [TPB * NCH];   // 15360 B

    const int cell0 = blockIdx.x * TPB;
    const long long fbase = (long long)cell0 * NCH;

    // ---- coalesced streaming stage: 960 float4 per tensor ----
    const float4* p4 = reinterpret_cast<const float4*>(pred + fbase);
    const float4* g4 = reinterpret_cast<const float4*>(gt   + fbase);
    float4* sp4 = reinterpret_cast<float4*>(s_pred);
    float4* sg4 = reinterpret_cast<float4*>(s_gt);
    const int n4 = TPB * NCH / 4;                  // 960
    #pragma unroll 4
    for (int i = threadIdx.x; i < n4; i += TPB) {
        sp4[i] = __ldcs(p4 + i);   // evict-first: zero cross-block reuse
        sg4[i] = __ldcs(g4 + i);
    }
    __syncthreads();

    float loss = 0.0f;
    const int cell = cell0 + threadIdx.x;
    if (cell < n_cells) {
        const float* p = s_pred + threadIdx.x * NCH;
        const float* g = s_gt   + threadIdx.x * NCH;

        const float gx = g[0], gy = g[1], gw = g[2], gh = g[3];
        const float obj   = (g[4] > 0.0f) ? 1.0f : 0.0f;
        const float noobj = 1.0f - obj;

        const float pc0 = p[4];
        const float pc1 = p[9];

        // no-object confidence loss (gt conf is 0 on noobj cells, both boxes)
        const float no_obj_term = noobj * (pc0 * pc0 + pc1 * pc1);

        // IoU of each predicted box vs gt box (corners = center +/- 3.5*wh)
        const float ghw = 3.5f * gw, ghh = 3.5f * gh;
        const float gx1 = gx - ghw, gx2 = gx + ghw;
        const float gy1 = gy - ghh, gy2 = gy + ghh;
        const float a2  = 49.0f * gw * gh;

        float iou[2];
        #pragma unroll
        for (int b = 0; b < 2; b++) {
            const float cx = p[b*5+0], cy = p[b*5+1];
            const float w  = p[b*5+2], h  = p[b*5+3];
            const float hw = 3.5f * w, hh = 3.5f * h;
            const float iw = fmaxf(fminf(cx + hw, gx2) - fmaxf(cx - hw, gx1), 0.0f);
            const float ih = fmaxf(fminf(cy + hh, gy2) - fmaxf(cy - hh, gy1), 0.0f);
            const float inter = iw * ih;
            const float a1 = 49.0f * w * h;
            iou[b] = inter / (a1 + a2 - inter);
        }

        // responsible box: argmax over 2 (first index wins ties, jnp semantics)
        const int   r       = (iou[1] > iou[0]) ? 1 : 0;
        const float max_iou = fmaxf(iou[0], iou[1]);
        const float* pr     = p + r * 5;
        const float pc_irr  = r ? pc0 : pc1;

        // coordinate loss (responsible box only)
        const float dx = pr[0] - gx;
        const float dy = pr[1] - gy;
        const float dw = sqrtf(pr[2]) - sqrtf(gw);
        const float dh = sqrtf(pr[3]) - sqrtf(gh);
        const float coord = dx*dx + dy*dy + dw*dw + dh*dh;

        // response (counted twice) & irresponse confidence losses
        const float dr = pr[4] - max_iou;
        const float resp_l   = dr * dr;
        const float irresp_l = pc_irr * pc_irr;

        // class loss over 20 channels
        float cls = 0.0f;
        #pragma unroll
        for (int c = 10; c < 30; c++) {
            const float d = p[c] - g[c];
            cls = fmaf(d, d, cls);
        }

        loss = obj * (5.0f * coord + 2.0f * resp_l + irresp_l + cls)
             + 0.5f * no_obj_term;
    }

    // ---- deterministic block reduction ----
    #pragma unroll
    for (int o = 16; o > 0; o >>= 1)
        loss += __shfl_down_sync(0xffffffffu, loss, o);

    __shared__ float s_warp[TPB / 32];
    const int lane = threadIdx.x & 31;
    const int wid  = threadIdx.x >> 5;
    if (lane == 0) s_warp[wid] = loss;
    __syncthreads();

    __shared__ bool s_is_last;
    if (threadIdx.x == 0) {
        g_partials[blockIdx.x] = s_warp[0] + s_warp[1] + s_warp[2] + s_warp[3];
        __threadfence();
        unsigned int done = atomicAdd(&g_count, 1u);
        s_is_last = (done == (unsigned int)(n_blocks - 1));
    }
    __syncthreads();

    // ---- last block folds the partials (fixed order -> deterministic) ----
    if (s_is_last) {
        float v = 0.0f;
        for (int i = threadIdx.x; i < n_blocks; i += TPB)
            v += g_partials[i];

        #pragma unroll
        for (int o = 16; o > 0; o >>= 1)
            v += __shfl_down_sync(0xffffffffu, v, o);

        if (lane == 0) s_warp[wid] = v;
        __syncthreads();
        if (threadIdx.x == 0) {
            out[0] = (s_warp[0] + s_warp[1] + s_warp[2] + s_warp[3]) * inv_batch;
            g_count = 0;   // reset for next graph replay
        }
    }
}

extern "C" void kernel_launch(void* const* d_in, const int* in_sizes, int n_in,
                              void* d_out, int out_size)
{
    const float* pred = (const float*)d_in[0];
    const float* gt   = (const float*)d_in[1];
    float* out = (float*)d_out;

    const int n_cells  = in_sizes[0] / NCH;          // 401408
    const int n_blocks = (n_cells + TPB - 1) / TPB;  // 3136
    const int batch    = n_cells / 49;               // 8192

    yolo_loss_fused<<<n_blocks, TPB>>>(pred, gt, out, n_cells, n_blocks,
                                       1.0f / (float)batch);
}

// round 3
// speedup vs baseline: 1.1082x; 1.1082x over previous
#include <cuda_runtime.h>

// Problem constants (fixed shapes: pred[8192,7,7,30], gt[8192,7,7,30])
#define NCH        30
#define TPB        128           // threads per block = cells per block
#define MAX_BLOCKS 4096          // 401408/128 = 3136 actual

// Scratch (no device allocation allowed -> device globals)
__device__ float        g_partials[MAX_BLOCKS];
__device__ unsigned int g_count = 0;   // blocks-done counter (reset by last block)

__global__ __launch_bounds__(TPB)
void yolo_loss_fused(const float* __restrict__ pred,
                     const float* __restrict__ gt,
                     float* __restrict__ out,
                     int n_cells, int n_blocks, float inv_batch)
{
    __shared__ float s_pred[TPB * NCH];   // 15360 B
    __shared__ float s_gt  [TPB * NCH];   // 15360 B

    const int cell0 = blockIdx.x * TPB;
    const long long fbase = (long long)cell0 * NCH;

    // ---- coalesced staging: 960 float4 per tensor (plain cached loads) ----
    const float4* p4 = reinterpret_cast<const float4*>(pred + fbase);
    const float4* g4 = reinterpret_cast<const float4*>(gt   + fbase);
    float4* sp4 = reinterpret_cast<float4*>(s_pred);
    float4* sg4 = reinterpret_cast<float4*>(s_gt);
    const int n4 = TPB * NCH / 4;                  // 960
    #pragma unroll 4
    for (int i = threadIdx.x; i < n4; i += TPB) {
        sp4[i] = p4[i];
        sg4[i] = g4[i];
    }
    __syncthreads();

    float loss = 0.0f;
    const int cell = cell0 + threadIdx.x;
    if (cell < n_cells) {
        const float* p = s_pred + threadIdx.x * NCH;
        const float* g = s_gt   + threadIdx.x * NCH;

        const float gx = g[0], gy = g[1], gw = g[2], gh = g[3];
        const float obj   = (g[4] > 0.0f) ? 1.0f : 0.0f;
        const float noobj = 1.0f - obj;

        const float pc0 = p[4];
        const float pc1 = p[9];

        // no-object confidence loss (gt conf is 0 on noobj cells, both boxes)
        const float no_obj_term = noobj * (pc0 * pc0 + pc1 * pc1);

        // IoU of each predicted box vs gt box (corners = center +/- 3.5*wh)
        const float ghw = 3.5f * gw, ghh = 3.5f * gh;
        const float gx1 = gx - ghw, gx2 = gx + ghw;
        const float gy1 = gy - ghh, gy2 = gy + ghh;
        const float a2  = 49.0f * gw * gh;

        float iou[2];
        #pragma unroll
        for (int b = 0; b < 2; b++) {
            const float cx = p[b*5+0], cy = p[b*5+1];
            const float w  = p[b*5+2], h  = p[b*5+3];
            const float hw = 3.5f * w, hh = 3.5f * h;
            const float iw = fmaxf(fminf(cx + hw, gx2) - fmaxf(cx - hw, gx1), 0.0f);
            const float ih = fmaxf(fminf(cy + hh, gy2) - fmaxf(cy - hh, gy1), 0.0f);
            const float inter = iw * ih;
            const float a1 = 49.0f * w * h;
            iou[b] = inter / (a1 + a2 - inter);
        }

        // responsible box: argmax over 2 (first index wins ties, jnp semantics)
        const int   r       = (iou[1] > iou[0]) ? 1 : 0;
        const float max_iou = fmaxf(iou[0], iou[1]);
        const float* pr     = p + r * 5;
        const float pc_irr  = r ? pc0 : pc1;

        // coordinate loss (responsible box only)
        const float dx = pr[0] - gx;
        const float dy = pr[1] - gy;
        const float dw = sqrtf(pr[2]) - sqrtf(gw);
        const float dh = sqrtf(pr[3]) - sqrtf(gh);
        const float coord = dx*dx + dy*dy + dw*dw + dh*dh;

        // response (counted twice) & irresponse confidence losses
        const float dr = pr[4] - max_iou;
        const float resp_l   = dr * dr;
        const float irresp_l = pc_irr * pc_irr;

        // class loss over 20 channels
        float cls = 0.0f;
        #pragma unroll
        for (int c = 10; c < 30; c++) {
            const float d = p[c] - g[c];
            cls = fmaf(d, d, cls);
        }

        loss = obj * (5.0f * coord + 2.0f * resp_l + irresp_l + cls)
             + 0.5f * no_obj_term;
    }

    // ---- deterministic block reduction ----
    #pragma unroll
    for (int o = 16; o > 0; o >>= 1)
        loss += __shfl_down_sync(0xffffffffu, loss, o);

    __shared__ float s_warp[TPB / 32];
    const int lane = threadIdx.x & 31;
    const int wid  = threadIdx.x >> 5;
    if (lane == 0) s_warp[wid] = loss;
    __syncthreads();

    __shared__ bool s_is_last;
    if (threadIdx.x == 0) {
        g_partials[blockIdx.x] = s_warp[0] + s_warp[1] + s_warp[2] + s_warp[3];
        __threadfence();
        unsigned int done = atomicAdd(&g_count, 1u);
        s_is_last = (done == (unsigned int)(n_blocks - 1));
    }
    __syncthreads();

    // ---- last block folds the partials (fixed order -> deterministic) ----
    if (s_is_last) {
        float v = 0.0f;
        for (int i = threadIdx.x; i < n_blocks; i += TPB)
            v += g_partials[i];

        #pragma unroll
        for (int o = 16; o > 0; o >>= 1)
            v += __shfl_down_sync(0xffffffffu, v, o);

        if (lane == 0) s_warp[wid] = v;
        __syncthreads();
        if (threadIdx.x == 0) {
            out[0] = (s_warp[0] + s_warp[1] + s_warp[2] + s_warp[3]) * inv_batch;
            g_count = 0;   // reset for next graph replay
        }
    }
}

extern "C" void kernel_launch(void* const* d_in, const int* in_sizes, int n_in,
                              void* d_out, int out_size)
{
    const float* pred = (const float*)d_in[0];
    const float* gt   = (const float*)d_in[1];
    float* out = (float*)d_out;

    const int n_cells  = in_sizes[0] / NCH;          // 401408
    const int n_blocks = (n_cells + TPB - 1) / TPB;  // 3136
    const int batch    = n_cells / 49;               // 8192

    yolo_loss_fused<<<n_blocks, TPB>>>(pred, gt, out, n_cells, n_blocks,
                                       1.0f / (float)batch);
}

// round 4
// speedup vs baseline: 1.3795x; 1.2448x over previous
#include <cuda_runtime.h>

// Fixed shapes: pred[8192,7,7,30], gt[8192,7,7,30] -> 401408 cells = 3136 tiles of 128
#define NCH            30
#define TPB            128
#define F4_PER_TENSOR  960        // 128 cells * 30 ch / 4
#define F4_PER_TILE    1920       // pred + gt
#define TILE_BYTES     (F4_PER_TILE * 16)          // 30720 B
#define SMEM_BYTES     (2 * TILE_BYTES)            // 61440 B (double buffer)
#define GRID_BLOCKS    456                         // 152 SMs * 3 CTAs -> one wave
#define MAX_PART       1024

// Scratch (no device allocation allowed -> device globals)
__device__ float        g_partials[MAX_PART];
__device__ unsigned int g_count = 0;

__device__ __forceinline__ float cell_loss(const float* __restrict__ p,
                                           const float* __restrict__ g)
{
    const float gx = g[0], gy = g[1], gw = g[2], gh = g[3];
    const float obj   = (g[4] > 0.0f) ? 1.0f : 0.0f;
    const float noobj = 1.0f - obj;

    const float pc0 = p[4];
    const float pc1 = p[9];

    // no-object confidence loss (gt conf 0 on noobj cells, both boxes)
    const float no_obj_term = noobj * (pc0 * pc0 + pc1 * pc1);

    // IoU of each predicted box vs gt box (corners = center +/- 3.5*wh)
    const float ghw = 3.5f * gw, ghh = 3.5f * gh;
    const float gx1 = gx - ghw, gx2 = gx + ghw;
    const float gy1 = gy - ghh, gy2 = gy + ghh;
    const float a2  = 49.0f * gw * gh;

    float iou[2];
    #pragma unroll
    for (int b = 0; b < 2; b++) {
        const float cx = p[b*5+0], cy = p[b*5+1];
        const float w  = p[b*5+2], h  = p[b*5+3];
        const float hw = 3.5f * w, hh = 3.5f * h;
        const float iw = fmaxf(fminf(cx + hw, gx2) - fmaxf(cx - hw, gx1), 0.0f);
        const float ih = fmaxf(fminf(cy + hh, gy2) - fmaxf(cy - hh, gy1), 0.0f);
        const float inter = iw * ih;
        const float a1 = 49.0f * w * h;
        iou[b] = inter / (a1 + a2 - inter);
    }

    // responsible box: argmax over 2 (first index wins ties, jnp semantics)
    const int   r       = (iou[1] > iou[0]) ? 1 : 0;
    const float max_iou = fmaxf(iou[0], iou[1]);
    const float* pr     = p + r * 5;
    const float pc_irr  = r ? pc0 : pc1;

    // coordinate loss (responsible box only)
    const float dx = pr[0] - gx;
    const float dy = pr[1] - gy;
    const float dw = sqrtf(pr[2]) - sqrtf(gw);
    const float dh = sqrtf(pr[3]) - sqrtf(gh);
    const float coord = dx*dx + dy*dy + dw*dw + dh*dh;

    // response (counted twice) & irresponse confidence losses
    const float dr = pr[4] - max_iou;
    const float resp_l   = dr * dr;
    const float irresp_l = pc_irr * pc_irr;

    // class loss over 20 channels
    float cls = 0.0f;
    #pragma unroll
    for (int c = 10; c < 30; c++) {
        const float d = p[c] - g[c];
        cls = fmaf(d, d, cls);
    }

    return obj * (5.0f * coord + 2.0f * resp_l + irresp_l + cls)
         + 0.5f * no_obj_term;
}

__global__ __launch_bounds__(TPB)
void yolo_loss_pipe(const float4* __restrict__ pred4,
                    const float4* __restrict__ gt4,
                    float* __restrict__ out,
                    int n_tiles, int gridsz, float inv_batch)
{
    extern __shared__ float4 smem[];   // [2][F4_PER_TILE]
    const int tid = threadIdx.x;

    // ---- async stage of one 128-cell tile (pred then gt) into buffer `buf`
    auto issue_tile = [&](int tile, int buf) {
        const long long base = (long long)tile * F4_PER_TENSOR;
        float4* dst = smem + buf * F4_PER_TILE;
        #pragma unroll
        for (int k = 0; k < F4_PER_TILE / TPB; k++) {      // 15 per thread
            const int i = tid + k * TPB;
            const float4* src = (i < F4_PER_TENSOR)
                              ? (pred4 + base + i)
                              : (gt4 + base + (i - F4_PER_TENSOR));
            unsigned saddr = (unsigned)__cvta_generic_to_shared(dst + i);
            asm volatile("cp.async.cg.shared.global [%0], [%1], 16;"
                         :: "r"(saddr), "l"(src));
        }
        asm volatile("cp.async.commit_group;" ::: "memory");
    };

    float acc = 0.0f;
    int t   = blockIdx.x;
    int buf = 0;

    if (t < n_tiles) issue_tile(t, 0);

    while (t < n_tiles) {
        const int tn = t + gridsz;
        if (tn < n_tiles) {
            issue_tile(tn, buf ^ 1);
            asm volatile("cp.async.wait_group 1;" ::: "memory");
        } else {
            asm volatile("cp.async.wait_group 0;" ::: "memory");
        }
        __syncthreads();   // all threads' async copies for `buf` visible block-wide

        const float* s_pred = reinterpret_cast<const float*>(smem + buf * F4_PER_TILE);
        const float* s_gt   = s_pred + F4_PER_TENSOR * 4;
        acc += cell_loss(s_pred + tid * NCH, s_gt + tid * NCH);

        __syncthreads();   // protect `buf` before next iteration prefetches into it
        buf ^= 1;
        t = tn;
    }

    // ---- deterministic block reduction (once per block) ----
    #pragma unroll
    for (int o = 16; o > 0; o >>= 1)
        acc += __shfl_down_sync(0xffffffffu, acc, o);

    __shared__ float s_warp[TPB / 32];
    const int lane = tid & 31;
    const int wid  = tid >> 5;
    if (lane == 0) s_warp[wid] = acc;
    __syncthreads();

    __shared__ bool s_is_last;
    if (tid == 0) {
        g_partials[blockIdx.x] = s_warp[0] + s_warp[1] + s_warp[2] + s_warp[3];
        __threadfence();
        unsigned int done = atomicAdd(&g_count, 1u);
        s_is_last = (done == (unsigned int)(gridDim.x - 1));
    }
    __syncthreads();

    // ---- last block folds 456 partials (fixed order -> deterministic) ----
    if (s_is_last) {
        float v = 0.0f;
        for (int i = tid; i < (int)gridDim.x; i += TPB)
            v += g_partials[i];

        #pragma unroll
        for (int o = 16; o > 0; o >>= 1)
            v += __shfl_down_sync(0xffffffffu, v, o);

        if (lane == 0) s_warp[wid] = v;
        __syncthreads();
        if (tid == 0) {
            out[0] = (s_warp[0] + s_warp[1] + s_warp[2] + s_warp[3]) * inv_batch;
            g_count = 0;   // reset for next graph replay
        }
    }
}

extern "C" void kernel_launch(void* const* d_in, const int* in_sizes, int n_in,
                              void* d_out, int out_size)
{
    const float4* pred4 = (const float4*)d_in[0];
    const float4* gt4   = (const float4*)d_in[1];
    float* out = (float*)d_out;

    const int n_cells = in_sizes[0] / NCH;      // 401408
    const int n_tiles = n_cells / TPB;          // 3136 (exact)
    const int batch   = n_cells / 49;           // 8192

    // opt-in to 61440 B dynamic smem (idempotent; not a stream op, capture-safe)
    static_assert(SMEM_BYTES == 61440, "");
    cudaFuncSetAttribute(yolo_loss_pipe,
                         cudaFuncAttributeMaxDynamicSharedMemorySize, SMEM_BYTES);

    yolo_loss_pipe<<<GRID_BLOCKS, TPB, SMEM_BYTES>>>(pred4, gt4, out,
                                                     n_tiles, GRID_BLOCKS,
                                                     1.0f / (float)batch);
}

// round 5
// speedup vs baseline: 1.5702x; 1.1382x over previous
#include <cuda_runtime.h>

// Fixed shapes: pred[8192,7,7,30], gt[8192,7,7,30]
// 401408 cells = 12544 warp-tiles of 32 cells
#define NCH        30
#define TPB        128
#define NWARPS_CTA 4
#define GRID_BLOCKS 456                       // 152 SMs * 3 CTAs -> one wave
#define WT_F4      240                        // 32 cells * 30 ch / 4 (per tensor)
#define STAGE_F4   (2 * WT_F4)                // 480 f4 = 7680 B (pred + gt)
#define WARP_SMEM_F4 (2 * STAGE_F4)           // double buffer = 960 f4
#define SMEM_BYTES (NWARPS_CTA * WARP_SMEM_F4 * 16)   // 61440 B
#define MAX_PART   1024

__device__ float        g_partials[MAX_PART];
__device__ unsigned int g_count = 0;

__device__ __forceinline__ float cell_loss(const float* __restrict__ p,
                                           const float* __restrict__ g)
{
    const float gx = g[0], gy = g[1], gw = g[2], gh = g[3];
    const float obj   = (g[4] > 0.0f) ? 1.0f : 0.0f;
    const float noobj = 1.0f - obj;

    const float pc0 = p[4];
    const float pc1 = p[9];

    const float no_obj_term = noobj * (pc0 * pc0 + pc1 * pc1);

    const float ghw = 3.5f * gw, ghh = 3.5f * gh;
    const float gx1 = gx - ghw, gx2 = gx + ghw;
    const float gy1 = gy - ghh, gy2 = gy + ghh;
    const float a2  = 49.0f * gw * gh;

    float iou[2];
    #pragma unroll
    for (int b = 0; b < 2; b++) {
        const float cx = p[b*5+0], cy = p[b*5+1];
        const float w  = p[b*5+2], h  = p[b*5+3];
        const float hw = 3.5f * w, hh = 3.5f * h;
        const float iw = fmaxf(fminf(cx + hw, gx2) - fmaxf(cx - hw, gx1), 0.0f);
        const float ih = fmaxf(fminf(cy + hh, gy2) - fmaxf(cy - hh, gy1), 0.0f);
        const float inter = iw * ih;
        const float a1 = 49.0f * w * h;
        iou[b] = inter / (a1 + a2 - inter);
    }

    const int   r       = (iou[1] > iou[0]) ? 1 : 0;
    const float max_iou = fmaxf(iou[0], iou[1]);
    const float* pr     = p + r * 5;
    const float pc_irr  = r ? pc0 : pc1;

    const float dx = pr[0] - gx;
    const float dy = pr[1] - gy;
    const float dw = sqrtf(pr[2]) - sqrtf(gw);
    const float dh = sqrtf(pr[3]) - sqrtf(gh);
    const float coord = dx*dx + dy*dy + dw*dw + dh*dh;

    const float dr = pr[4] - max_iou;
    const float resp_l   = dr * dr;
    const float irresp_l = pc_irr * pc_irr;

    float cls = 0.0f;
    #pragma unroll
    for (int c = 10; c < 30; c++) {
        const float d = p[c] - g[c];
        cls = fmaf(d, d, cls);
    }

    return obj * (5.0f * coord + 2.0f * resp_l + irresp_l + cls)
         + 0.5f * no_obj_term;
}

__global__ __launch_bounds__(TPB)
void yolo_loss_warp_pipe(const float4* __restrict__ pred4,
                         const float4* __restrict__ gt4,
                         float* __restrict__ out,
                         int n_wtiles, int n_wpipes, float inv_batch)
{
    extern __shared__ float4 smem[];           // [4 warps][2 bufs][480 f4]
    const int tid  = threadIdx.x;
    const int lane = tid & 31;
    const int wid  = tid >> 5;
    float4* wsm = smem + wid * WARP_SMEM_F4;

    // ---- per-warp async stage: one 32-cell tile into buffer `buf` ----
    auto issue = [&](int tile, int buf) {
        const float4* psrc = pred4 + (long long)tile * WT_F4;
        const float4* gsrc = gt4   + (long long)tile * WT_F4;
        float4* dst = wsm + buf * STAGE_F4;
        #pragma unroll
        for (int k = 0; k < STAGE_F4 / 32; k++) {          // 15 per lane
            const int i = lane + k * 32;
            const float4* src = (i < WT_F4) ? (psrc + i) : (gsrc + (i - WT_F4));
            unsigned saddr = (unsigned)__cvta_generic_to_shared(dst + i);
            asm volatile("cp.async.cg.shared.global [%0], [%1], 16;"
                         :: "r"(saddr), "l"(src));
        }
        asm volatile("cp.async.commit_group;" ::: "memory");
    };

    float acc = 0.0f;
    const int gw = blockIdx.x * NWARPS_CTA + wid;   // global warp-pipeline id
    int t   = gw;
    int buf = 0;

    if (t < n_wtiles) issue(t, 0);

    while (t < n_wtiles) {
        const int tn = t + n_wpipes;
        if (tn < n_wtiles) {
            issue(tn, buf ^ 1);
            asm volatile("cp.async.wait_group 1;" ::: "memory");
        } else {
            asm volatile("cp.async.wait_group 0;" ::: "memory");
        }
        __syncwarp();   // cross-lane: cp.async writes visible to all lanes

        const float* base = reinterpret_cast<const float*>(wsm + buf * STAGE_F4);
        acc += cell_loss(base + lane * NCH,
                         base + WT_F4 * 4 + lane * NCH);

        __syncwarp();   // compute reads done before buf is refilled next iter
        buf ^= 1;
        t = tn;
    }

    // ---- per-warp then block reduction (deterministic) ----
    #pragma unroll
    for (int o = 16; o > 0; o >>= 1)
        acc += __shfl_down_sync(0xffffffffu, acc, o);

    __shared__ float s_warp[NWARPS_CTA];
    if (lane == 0) s_warp[wid] = acc;
    __syncthreads();

    __shared__ bool s_is_last;
    if (tid == 0) {
        g_partials[blockIdx.x] = s_warp[0] + s_warp[1] + s_warp[2] + s_warp[3];
        __threadfence();
        unsigned int done = atomicAdd(&g_count, 1u);
        s_is_last = (done == (unsigned int)(gridDim.x - 1));
    }
    __syncthreads();

    // ---- last block folds the partials (fixed order -> deterministic) ----
    if (s_is_last) {
        float v = 0.0f;
        for (int i = tid; i < (int)gridDim.x; i += TPB)
            v += g_partials[i];

        #pragma unroll
        for (int o = 16; o > 0; o >>= 1)
            v += __shfl_down_sync(0xffffffffu, v, o);

        if (lane == 0) s_warp[wid] = v;
        __syncthreads();
        if (tid == 0) {
            out[0] = (s_warp[0] + s_warp[1] + s_warp[2] + s_warp[3]) * inv_batch;
            g_count = 0;   // reset for next graph replay
        }
    }
}

extern "C" void kernel_launch(void* const* d_in, const int* in_sizes, int n_in,
                              void* d_out, int out_size)
{
    const float4* pred4 = (const float4*)d_in[0];
    const float4* gt4   = (const float4*)d_in[1];
    float* out = (float*)d_out;

    const int n_cells  = in_sizes[0] / NCH;       // 401408
    const int n_wtiles = n_cells / 32;            // 12544 (exact)
    const int n_wpipes = GRID_BLOCKS * NWARPS_CTA;// 1824
    const int batch    = n_cells / 49;            // 8192

    cudaFuncSetAttribute(yolo_loss_warp_pipe,
                         cudaFuncAttributeMaxDynamicSharedMemorySize, SMEM_BYTES);

    yolo_loss_warp_pipe<<<GRID_BLOCKS, TPB, SMEM_BYTES>>>(pred4, gt4, out,
                                                          n_wtiles, n_wpipes,
                                                          1.0f / (float)batch);
}